// round 12
// baseline (speedup 1.0000x reference)
#include <cuda_runtime.h>
#include <cuda_bf16.h>
#include <math.h>
#include <stdint.h>

#define B_   16
#define L_   1024
#define C_   64
#define K_   10
#define H_   1024
#define M_   (B_*L_)        /* 16384 rows */
#define NOUT 1024           /* active half of COUT=2048 */
#define COUT_ 2048

/* scratch (allocation-free rule: __device__ globals) */
__device__ __nv_bfloat16 g_ha_hi[M_ * H_];   /* 32 MB */
__device__ __nv_bfloat16 g_ha_lo[M_ * H_];   /* 32 MB */
__device__ __nv_bfloat16 g_w2_hi[NOUT * H_]; /*  2 MB: [n][k] */
__device__ __nv_bfloat16 g_w2_lo[NOUT * H_]; /*  2 MB */
__device__ float g_nn[M_ * NOUT];            /* 64 MB */
__device__ float g_part[2048];

/* ---------------- helpers ---------------- */
__device__ __forceinline__ uint32_t smem_u32(const void* p) {
    uint32_t a;
    asm("{ .reg .u64 t; cvta.to.shared.u64 t, %1; cvt.u32.u64 %0, t; }" : "=r"(a) : "l"(p));
    return a;
}
#define CPA16(dst, src) asm volatile("cp.async.cg.shared.global [%0], [%1], 16;" :: "r"(dst), "l"(src))
#define CPA_COMMIT()    asm volatile("cp.async.commit_group;")
#define CPA_WAIT(n)     asm volatile("cp.async.wait_group %0;" :: "n"(n) : "memory")

__device__ __forceinline__ void ldm_x4(uint32_t& r0, uint32_t& r1, uint32_t& r2, uint32_t& r3,
                                       uint32_t addr) {
    asm volatile("ldmatrix.sync.aligned.m8n8.x4.shared.b16 {%0,%1,%2,%3}, [%4];"
                 : "=r"(r0), "=r"(r1), "=r"(r2), "=r"(r3) : "r"(addr));
}
__device__ __forceinline__ void mma_bf16(float* d, const uint32_t* a, const uint32_t* b) {
    asm volatile("mma.sync.aligned.m16n8k16.row.col.f32.bf16.bf16.f32 "
                 "{%0,%1,%2,%3}, {%4,%5,%6,%7}, {%8,%9}, {%0,%1,%2,%3};"
                 : "+f"(d[0]), "+f"(d[1]), "+f"(d[2]), "+f"(d[3])
                 : "r"(a[0]), "r"(a[1]), "r"(a[2]), "r"(a[3]), "r"(b[0]), "r"(b[1]));
}

__device__ __forceinline__ float gelu_tanh(float x) {
    const float k0 = 0.7978845608028654f, k1 = 0.044715f;
    float t = tanhf(k0 * (x + k1 * x * x * x));
    return 0.5f * x * (1.0f + t);
}

/* ------------------------------------------------------------------ */
/* w2 transpose+split: hi/lo bf16 of w2[k][1024+n] at [n][k]           */
/* ------------------------------------------------------------------ */
__global__ __launch_bounds__(256) void w2t_kernel(const float* __restrict__ w2)
{
    __shared__ float t[32][33];
    int k0 = blockIdx.y * 32, n0 = blockIdx.x * 32;
    int tx = threadIdx.x & 31, ty = threadIdx.x >> 5;   /* 32 x 8 */
    #pragma unroll
    for (int j = 0; j < 32; j += 8)
        t[ty + j][tx] = w2[(size_t)(k0 + ty + j) * COUT_ + 1024 + n0 + tx];
    __syncthreads();
    #pragma unroll
    for (int j = 0; j < 32; j += 8) {
        float v = t[tx][ty + j];
        __nv_bfloat16 hi = __float2bfloat16(v);
        __nv_bfloat16 lo = __float2bfloat16(v - __bfloat162float(hi));
        size_t idx = (size_t)(n0 + ty + j) * H_ + k0 + tx;
        g_w2_hi[idx] = hi;
        g_w2_lo[idx] = lo;
    }
}

/* ------------------------------------------------------------------ */
/* GEMM1: h = gelu(z_in @ w1 + b1), K truncated to 32 (mask zeroes top)*/
/* epilogue stores bf16 hi + lo                                        */
/* ------------------------------------------------------------------ */
__global__ __launch_bounds__(256) void gemm1_kernel(
    const float* __restrict__ z, const float* __restrict__ mask,
    const float* __restrict__ w1, const float* __restrict__ b1)
{
    __shared__ float zs[32][64];
    __shared__ float ws[32][128];

    const int m0 = blockIdx.y * 64;
    const int n0 = blockIdx.x * 128;
    const int tid = threadIdx.x;

    #pragma unroll
    for (int s = 0; s < 2; s++) {
        int idx = tid + 256 * s;
        int row = idx >> 3, q = idx & 7;
        float4 v = *reinterpret_cast<const float4*>(z + (size_t)(m0 + row) * C_ + q * 4);
        int c = q * 4;
        zs[c + 0][row] = v.x * __ldg(mask + c + 0);
        zs[c + 1][row] = v.y * __ldg(mask + c + 1);
        zs[c + 2][row] = v.z * __ldg(mask + c + 2);
        zs[c + 3][row] = v.w * __ldg(mask + c + 3);
    }
    #pragma unroll
    for (int s = 0; s < 4; s++) {
        int idx = tid + 256 * s;
        int c = idx >> 5, j = idx & 31;
        *reinterpret_cast<float4*>(&ws[c][j * 4]) =
            *reinterpret_cast<const float4*>(w1 + (size_t)c * H_ + n0 + j * 4);
    }
    __syncthreads();

    const int ty = tid >> 5, tx = tid & 31;
    float acc[8][4];
    #pragma unroll
    for (int i = 0; i < 8; i++)
        #pragma unroll
        for (int j = 0; j < 4; j++) acc[i][j] = 0.0f;

    #pragma unroll 8
    for (int c = 0; c < 32; c++) {
        float4 b4 = *reinterpret_cast<float4*>(&ws[c][tx * 4]);
        float a[8];
        *reinterpret_cast<float4*>(a)     = *reinterpret_cast<float4*>(&zs[c][ty * 8]);
        *reinterpret_cast<float4*>(a + 4) = *reinterpret_cast<float4*>(&zs[c][ty * 8 + 4]);
        #pragma unroll
        for (int i = 0; i < 8; i++) {
            acc[i][0] += a[i] * b4.x; acc[i][1] += a[i] * b4.y;
            acc[i][2] += a[i] * b4.z; acc[i][3] += a[i] * b4.w;
        }
    }

    float4 bb = *reinterpret_cast<const float4*>(b1 + n0 + tx * 4);
    #pragma unroll
    for (int i = 0; i < 8; i++) {
        int row = m0 + ty * 8 + i;
        float o[4];
        o[0] = gelu_tanh(acc[i][0] + bb.x);
        o[1] = gelu_tanh(acc[i][1] + bb.y);
        o[2] = gelu_tanh(acc[i][2] + bb.z);
        o[3] = gelu_tanh(acc[i][3] + bb.w);
        __nv_bfloat162 h0, h1, l0, l1;
        h0.x = __float2bfloat16(o[0]); h0.y = __float2bfloat16(o[1]);
        h1.x = __float2bfloat16(o[2]); h1.y = __float2bfloat16(o[3]);
        l0.x = __float2bfloat16(o[0] - __bfloat162float(h0.x));
        l0.y = __float2bfloat16(o[1] - __bfloat162float(h0.y));
        l1.x = __float2bfloat16(o[2] - __bfloat162float(h1.x));
        l1.y = __float2bfloat16(o[3] - __bfloat162float(h1.y));
        size_t off = (size_t)row * H_ + n0 + tx * 4;
        *reinterpret_cast<uint2*>(g_ha_hi + off) = make_uint2(*(uint32_t*)&h0, *(uint32_t*)&h1);
        *reinterpret_cast<uint2*>(g_ha_lo + off) = make_uint2(*(uint32_t*)&l0, *(uint32_t*)&l1);
    }
}

/* ------------------------------------------------------------------ */
/* GEMM2: 3xBF16 split-precision, BM=128 BN=128 BK=32, 256 threads     */
/* 3-stage cp.async pipeline (one __syncthreads per k-tile);           */
/* per k-tile load A_hi,A_lo,B_hi,B_lo ONCE; 3 mma phases from smem    */
/* 8 warps = 2(M) x 4(N), warp tile 64x32 (verified fragment code)     */
/* ------------------------------------------------------------------ */
#define G2_NT 32
#define ST_SZ  32768
#define G2_SMEM (3 * ST_SZ)   /* 96 KB dynamic, 3 stages */

__global__ __launch_bounds__(256) void gemm2_mma_kernel(const float* __restrict__ b2)
{
    extern __shared__ __align__(16) char smem[];
    const uint32_t sb = smem_u32(smem);

    const int tid = threadIdx.x;
    const int wid = tid >> 5, lid = tid & 31;
    const int m0 = blockIdx.y * 128;
    const int n0 = blockIdx.x * 128;
    const int wm = (wid >> 2) * 64;
    const int wn = (wid & 3) * 32;

    const __nv_bfloat16* srcs[4] = {
        g_ha_hi + (size_t)m0 * H_,
        g_ha_lo + (size_t)m0 * H_,
        g_w2_hi + (size_t)n0 * H_,
        g_w2_lo + (size_t)n0 * H_
    };

    /* load one K-tile into stage st: 4 parts x 512 chunks of 16B */
    auto load_tile = [&](int kt, int st) {
        uint32_t base = sb + st * ST_SZ;
        #pragma unroll
        for (int s = 0; s < 8; s++) {
            int idx = tid + 256 * s;          /* 0..2047 */
            int part = idx >> 9;              /* 0..3 */
            int i2 = idx & 511;
            int row = i2 >> 2, seg = i2 & 3;
            uint32_t dst = (uint32_t)(part * 8192 + row * 64 + ((seg ^ ((row >> 1) & 3)) << 4));
            CPA16(base + dst, srcs[part] + (size_t)row * H_ + kt * 32 + seg * 8);
        }
        CPA_COMMIT();
    };

    float acc[4][4][4];
    #pragma unroll
    for (int i = 0; i < 4; i++)
        #pragma unroll
        for (int j = 0; j < 4; j++)
            #pragma unroll
            for (int q = 0; q < 4; q++) acc[i][j][q] = 0.0f;

    load_tile(0, 0);
    load_tile(1, 1);

    for (int kt = 0; kt < G2_NT; kt++) {
        if (kt < G2_NT - 1) { CPA_WAIT(1); } else { CPA_WAIT(0); }
        __syncthreads();
        if (kt + 2 < G2_NT) load_tile(kt + 2, (kt + 2) % 3);

        uint32_t stage = sb + (kt % 3) * ST_SZ;
        /* 3 phases: (Ahi,Bhi), (Ahi,Blo), (Alo,Bhi) */
        #pragma unroll
        for (int ph = 0; ph < 3; ph++) {
            uint32_t abase = stage + ((ph == 2) ? 8192 : 0);
            uint32_t bbase = stage + ((ph == 1) ? 24576 : 16384);
            #pragma unroll
            for (int kh = 0; kh < 2; kh++) {
                uint32_t af[4][4];
                #pragma unroll
                for (int mt = 0; mt < 4; mt++) {
                    int row = wm + mt * 16 + (lid & 15);
                    int ch  = (kh * 2 + (lid >> 4)) ^ ((row >> 1) & 3);
                    ldm_x4(af[mt][0], af[mt][1], af[mt][2], af[mt][3],
                           abase + (uint32_t)(row * 64 + ch * 16));
                }
                uint32_t bfr[2][4];
                #pragma unroll
                for (int np = 0; np < 2; np++) {
                    int row = wn + np * 16 + ((lid >> 4) * 8) + (lid & 7);
                    int ch  = (kh * 2 + ((lid >> 3) & 1)) ^ ((row >> 1) & 3);
                    ldm_x4(bfr[np][0], bfr[np][1], bfr[np][2], bfr[np][3],
                           bbase + (uint32_t)(row * 64 + ch * 16));
                }
                #pragma unroll
                for (int mt = 0; mt < 4; mt++)
                    #pragma unroll
                    for (int nt = 0; nt < 4; nt++)
                        mma_bf16(acc[mt][nt], af[mt], &bfr[nt >> 1][(nt & 1) * 2]);
            }
        }
    }

    /* epilogue: + bias, direct float2 stores */
    #pragma unroll
    for (int nt = 0; nt < 4; nt++) {
        int col = n0 + wn + nt * 8 + (lid & 3) * 2;
        float bx = __ldg(b2 + 1024 + col);
        float by = __ldg(b2 + 1024 + col + 1);
        #pragma unroll
        for (int mt = 0; mt < 4; mt++) {
            int r0 = m0 + wm + mt * 16 + (lid >> 2);
            float2 v0 = make_float2(acc[mt][nt][0] + bx, acc[mt][nt][1] + by);
            float2 v1 = make_float2(acc[mt][nt][2] + bx, acc[mt][nt][3] + by);
            *reinterpret_cast<float2*>(g_nn + (size_t)r0 * NOUT + col) = v0;
            *reinterpret_cast<float2*>(g_nn + (size_t)(r0 + 8) * NOUT + col) = v1;
        }
    }
}

/* ------------------------------------------------------------------ */
/* Postproc: per (row, c>=32) mixture-CDF math (accurate libm)         */
/* ------------------------------------------------------------------ */
__global__ __launch_bounds__(256) void post_kernel(
    const float* __restrict__ z, const float* __restrict__ mask,
    const float* __restrict__ sfv, const float* __restrict__ msfv,
    float* __restrict__ out)
{
    __shared__ float red[256];
    const int tid = threadIdx.x;
    const int rl = tid >> 5, cl = tid & 31;
    const int row = blockIdx.x * 8 + rl;
    const int c = 32 + cl;

    {
        float mlow = __ldg(mask + cl);
        out[(size_t)row * C_ + cl] = z[(size_t)row * C_ + cl] * mlow;
    }

    float p[32];
    {
        const float* pp = g_nn + (size_t)row * NOUT + cl * 32;
        #pragma unroll
        for (int q = 0; q < 32; q += 4) {
            float4 v = *reinterpret_cast<const float4*>(pp + q);
            p[q] = v.x; p[q+1] = v.y; p[q+2] = v.z; p[q+3] = v.w;
        }
    }

    const float zc = z[(size_t)row * C_ + c];
    const float maskv = __ldg(mask + c);
    const float cm = 1.0f - maskv;

    float sf = expf(__ldg(sfv + c));
    float t  = p[0] * cm;
    float ls = tanhf(p[1] / fmaxf(sf, 1.0f)) * sf * cm;

    float lp[K_], aa[K_], bbk[K_];
    float mx0 = -INFINITY, mxA = -INFINITY, mxB = -INFINITY;
    #pragma unroll
    for (int k = 0; k < K_; k++) { lp[k] = p[2 + k] * cm; mx0 = fmaxf(mx0, lp[k]); }
    #pragma unroll
    for (int k = 0; k < K_; k++) {
        float msf = expf(__ldg(msfv + c * K_ + k));
        float mls = tanhf(p[22 + k] / fmaxf(msf, 1.0f)) * msf * cm;
        float mt  = p[12 + k] * cm;
        float u   = (zc - mt) * expf(-mls);
        float e   = expf(-fabsf(u));
        float l1  = log1pf(e);
        float logsig = fminf(u, 0.0f) - l1;
        float sp     = fmaxf(u, 0.0f) + l1;
        aa[k]  = lp[k] + logsig;
        bbk[k] = lp[k] + u - mls - 2.0f * sp;
        mxA = fmaxf(mxA, aa[k]);
        mxB = fmaxf(mxB, bbk[k]);
    }
    float s0 = 0.0f, sA = 0.0f, sB = 0.0f;
    #pragma unroll
    for (int k = 0; k < K_; k++) {
        s0 += expf(lp[k] - mx0); sA += expf(aa[k] - mxA); sB += expf(bbk[k] - mxB);
    }
    float lse0 = mx0 + logf(s0);
    float lseA = mxA + logf(sA);
    float lseB = mxB + logf(sB);

    float log_cdf = lseA - lse0;
    float p_cdf   = expf(log_cdf);
    float z_logit = -logf(fmaxf(1.0f / p_cdf - 1.0f, 1e-22f));
    float mixt_ldj = -logf(fmaxf(p_cdf, 1e-22f)) - logf(fmaxf(1.0f - p_cdf, 1e-22f));
    float logistic_ldj = lseB - lse0;

    float zo = (z_logit + t) * expf(ls);
    zo = zo * cm + zc * maskv;
    out[(size_t)row * C_ + c] = zo;

    red[tid] = cm * (ls + mixt_ldj + logistic_ldj);
    __syncthreads();
    for (int s = 128; s > 0; s >>= 1) {
        if (tid < s) red[tid] += red[tid + s];
        __syncthreads();
    }
    if (tid == 0) g_part[blockIdx.x] = red[0];
}

__global__ __launch_bounds__(128) void reduce_kernel(float* __restrict__ out)
{
    __shared__ float red[128];
    const int b = blockIdx.x, tid = threadIdx.x;
    red[tid] = g_part[b * 128 + tid];
    __syncthreads();
    for (int s = 64; s > 0; s >>= 1) {
        if (tid < s) red[tid] += red[tid + s];
        __syncthreads();
    }
    if (tid == 0) out[(size_t)M_ * C_ + b] = red[0];
}

extern "C" void kernel_launch(void* const* d_in, const int* in_sizes, int n_in,
                              void* d_out, int out_size)
{
    const float* z    = (const float*)d_in[0];
    const float* mask = (const float*)d_in[1];
    const float* w1   = (const float*)d_in[2];
    const float* b1   = (const float*)d_in[3];
    const float* w2   = (const float*)d_in[4];
    const float* b2   = (const float*)d_in[5];
    const float* sfv  = (const float*)d_in[6];
    const float* msfv = (const float*)d_in[7];
    float* out = (float*)d_out;

    cudaFuncSetAttribute(gemm2_mma_kernel,
                         cudaFuncAttributeMaxDynamicSharedMemorySize, G2_SMEM);

    dim3 gt(NOUT / 32, H_ / 32);
    w2t_kernel<<<gt, 256>>>(w2);

    dim3 g1(H_ / 128, M_ / 64);
    gemm1_kernel<<<g1, 256>>>(z, mask, w1, b1);

    dim3 g2(NOUT / 128, M_ / 128);   /* (8, 128) = 1024 CTAs */
    gemm2_mma_kernel<<<g2, 256, G2_SMEM>>>(b2);

    post_kernel<<<M_ / 8, 256>>>(z, mask, sfv, msfv, out);
    reduce_kernel<<<B_, 128>>>(out);
}

// round 13
// speedup vs baseline: 1.1410x; 1.1410x over previous
#include <cuda_runtime.h>
#include <cuda_bf16.h>
#include <math.h>
#include <stdint.h>

#define B_   16
#define L_   1024
#define C_   64
#define K_   10
#define H_   1024
#define M_   (B_*L_)        /* 16384 rows */
#define NOUT 1024           /* active half of COUT=2048 */
#define COUT_ 2048

/* scratch (allocation-free rule: __device__ globals) */
__device__ __nv_bfloat16 g_ha_hi[M_ * H_];   /* 32 MB */
__device__ __nv_bfloat16 g_ha_lo[M_ * H_];   /* 32 MB */
__device__ __nv_bfloat16 g_w2_hi[NOUT * H_]; /*  2 MB: [n][k] */
__device__ __nv_bfloat16 g_w2_lo[NOUT * H_]; /*  2 MB */
__device__ float g_part[1024];               /* per-CTA ldj partials */

/* ---------------- helpers ---------------- */
__device__ __forceinline__ uint32_t smem_u32(const void* p) {
    uint32_t a;
    asm("{ .reg .u64 t; cvta.to.shared.u64 t, %1; cvt.u32.u64 %0, t; }" : "=r"(a) : "l"(p));
    return a;
}
#define CPA16(dst, src) asm volatile("cp.async.cg.shared.global [%0], [%1], 16;" :: "r"(dst), "l"(src))
#define CPA_COMMIT()    asm volatile("cp.async.commit_group;")
#define CPA_WAIT(n)     asm volatile("cp.async.wait_group %0;" :: "n"(n) : "memory")

__device__ __forceinline__ void ldm_x4(uint32_t& r0, uint32_t& r1, uint32_t& r2, uint32_t& r3,
                                       uint32_t addr) {
    asm volatile("ldmatrix.sync.aligned.m8n8.x4.shared.b16 {%0,%1,%2,%3}, [%4];"
                 : "=r"(r0), "=r"(r1), "=r"(r2), "=r"(r3) : "r"(addr));
}
__device__ __forceinline__ void mma_bf16(float* d, const uint32_t* a, const uint32_t* b) {
    asm volatile("mma.sync.aligned.m16n8k16.row.col.f32.bf16.bf16.f32 "
                 "{%0,%1,%2,%3}, {%4,%5,%6,%7}, {%8,%9}, {%0,%1,%2,%3};"
                 : "+f"(d[0]), "+f"(d[1]), "+f"(d[2]), "+f"(d[3])
                 : "r"(a[0]), "r"(a[1]), "r"(a[2]), "r"(a[3]), "r"(b[0]), "r"(b[1]));
}

__device__ __forceinline__ float gelu_tanh(float x) {
    const float k0 = 0.7978845608028654f, k1 = 0.044715f;
    float t = tanhf(k0 * (x + k1 * x * x * x));
    return 0.5f * x * (1.0f + t);
}

/* ------------------------------------------------------------------ */
/* w2 transpose+split: hi/lo bf16 of w2[k][1024+n] at [n][k]           */
/* ------------------------------------------------------------------ */
__global__ __launch_bounds__(256) void w2t_kernel(const float* __restrict__ w2)
{
    __shared__ float t[32][33];
    int k0 = blockIdx.y * 32, n0 = blockIdx.x * 32;
    int tx = threadIdx.x & 31, ty = threadIdx.x >> 5;   /* 32 x 8 */
    #pragma unroll
    for (int j = 0; j < 32; j += 8)
        t[ty + j][tx] = w2[(size_t)(k0 + ty + j) * COUT_ + 1024 + n0 + tx];
    __syncthreads();
    #pragma unroll
    for (int j = 0; j < 32; j += 8) {
        float v = t[tx][ty + j];
        __nv_bfloat16 hi = __float2bfloat16(v);
        __nv_bfloat16 lo = __float2bfloat16(v - __bfloat162float(hi));
        size_t idx = (size_t)(n0 + ty + j) * H_ + k0 + tx;
        g_w2_hi[idx] = hi;
        g_w2_lo[idx] = lo;
    }
}

/* ------------------------------------------------------------------ */
/* GEMM1: h = gelu(z_in @ w1 + b1), K truncated to 32 (mask zeroes top)*/
/* epilogue stores bf16 hi + lo                                        */
/* ------------------------------------------------------------------ */
__global__ __launch_bounds__(256) void gemm1_kernel(
    const float* __restrict__ z, const float* __restrict__ mask,
    const float* __restrict__ w1, const float* __restrict__ b1)
{
    __shared__ float zs[32][64];
    __shared__ float ws[32][128];

    const int m0 = blockIdx.y * 64;
    const int n0 = blockIdx.x * 128;
    const int tid = threadIdx.x;

    #pragma unroll
    for (int s = 0; s < 2; s++) {
        int idx = tid + 256 * s;
        int row = idx >> 3, q = idx & 7;
        float4 v = *reinterpret_cast<const float4*>(z + (size_t)(m0 + row) * C_ + q * 4);
        int c = q * 4;
        zs[c + 0][row] = v.x * __ldg(mask + c + 0);
        zs[c + 1][row] = v.y * __ldg(mask + c + 1);
        zs[c + 2][row] = v.z * __ldg(mask + c + 2);
        zs[c + 3][row] = v.w * __ldg(mask + c + 3);
    }
    #pragma unroll
    for (int s = 0; s < 4; s++) {
        int idx = tid + 256 * s;
        int c = idx >> 5, j = idx & 31;
        *reinterpret_cast<float4*>(&ws[c][j * 4]) =
            *reinterpret_cast<const float4*>(w1 + (size_t)c * H_ + n0 + j * 4);
    }
    __syncthreads();

    const int ty = tid >> 5, tx = tid & 31;
    float acc[8][4];
    #pragma unroll
    for (int i = 0; i < 8; i++)
        #pragma unroll
        for (int j = 0; j < 4; j++) acc[i][j] = 0.0f;

    #pragma unroll 8
    for (int c = 0; c < 32; c++) {
        float4 b4 = *reinterpret_cast<float4*>(&ws[c][tx * 4]);
        float a[8];
        *reinterpret_cast<float4*>(a)     = *reinterpret_cast<float4*>(&zs[c][ty * 8]);
        *reinterpret_cast<float4*>(a + 4) = *reinterpret_cast<float4*>(&zs[c][ty * 8 + 4]);
        #pragma unroll
        for (int i = 0; i < 8; i++) {
            acc[i][0] += a[i] * b4.x; acc[i][1] += a[i] * b4.y;
            acc[i][2] += a[i] * b4.z; acc[i][3] += a[i] * b4.w;
        }
    }

    float4 bb = *reinterpret_cast<const float4*>(b1 + n0 + tx * 4);
    #pragma unroll
    for (int i = 0; i < 8; i++) {
        int row = m0 + ty * 8 + i;
        float o[4];
        o[0] = gelu_tanh(acc[i][0] + bb.x);
        o[1] = gelu_tanh(acc[i][1] + bb.y);
        o[2] = gelu_tanh(acc[i][2] + bb.z);
        o[3] = gelu_tanh(acc[i][3] + bb.w);
        __nv_bfloat162 h0, h1, l0, l1;
        h0.x = __float2bfloat16(o[0]); h0.y = __float2bfloat16(o[1]);
        h1.x = __float2bfloat16(o[2]); h1.y = __float2bfloat16(o[3]);
        l0.x = __float2bfloat16(o[0] - __bfloat162float(h0.x));
        l0.y = __float2bfloat16(o[1] - __bfloat162float(h0.y));
        l1.x = __float2bfloat16(o[2] - __bfloat162float(h1.x));
        l1.y = __float2bfloat16(o[3] - __bfloat162float(h1.y));
        size_t off = (size_t)row * H_ + n0 + tx * 4;
        *reinterpret_cast<uint2*>(g_ha_hi + off) = make_uint2(*(uint32_t*)&h0, *(uint32_t*)&h1);
        *reinterpret_cast<uint2*>(g_ha_lo + off) = make_uint2(*(uint32_t*)&l0, *(uint32_t*)&l1);
    }
}

/* ------------------------------------------------------------------ */
/* GEMM2 + fused post: 3xBF16 split-precision, BM=128 BN=128 BK=32     */
/* mainloop: 3-stage cp.async pipeline, 3 mma phases per k-tile.       */
/* epilogue: acc+bias -> smem stage -> per-(row,channel) mixture-CDF   */
/* math (accurate libm), z_out direct, ldj partial -> g_part[CTA].     */
/* ------------------------------------------------------------------ */
#define G2_NT 32
#define ST_SZ  32768
#define G2_SMEM (3 * ST_SZ)   /* 96 KB dynamic */

__global__ __launch_bounds__(256, 2) void gemm2_fused_kernel(
    const float* __restrict__ b2,
    const float* __restrict__ z, const float* __restrict__ mask,
    const float* __restrict__ sfv, const float* __restrict__ msfv,
    float* __restrict__ out)
{
    extern __shared__ __align__(16) char smem[];
    const uint32_t sb = smem_u32(smem);

    const int tid = threadIdx.x;
    const int wid = tid >> 5, lid = tid & 31;
    const int m0 = blockIdx.y * 128;
    const int n0 = blockIdx.x * 128;
    const int wm = (wid >> 2) * 64;
    const int wn = (wid & 3) * 32;

    const __nv_bfloat16* srcs[4] = {
        g_ha_hi + (size_t)m0 * H_,
        g_ha_lo + (size_t)m0 * H_,
        g_w2_hi + (size_t)n0 * H_,
        g_w2_lo + (size_t)n0 * H_
    };

    auto load_tile = [&](int kt, int st) {
        uint32_t base = sb + st * ST_SZ;
        #pragma unroll
        for (int s = 0; s < 8; s++) {
            int idx = tid + 256 * s;          /* 0..2047 */
            int part = idx >> 9;              /* 0..3 */
            int i2 = idx & 511;
            int row = i2 >> 2, seg = i2 & 3;
            uint32_t dst = (uint32_t)(part * 8192 + row * 64 + ((seg ^ ((row >> 1) & 3)) << 4));
            CPA16(base + dst, srcs[part] + (size_t)row * H_ + kt * 32 + seg * 8);
        }
        CPA_COMMIT();
    };

    float acc[4][4][4];
    #pragma unroll
    for (int i = 0; i < 4; i++)
        #pragma unroll
        for (int j = 0; j < 4; j++)
            #pragma unroll
            for (int q = 0; q < 4; q++) acc[i][j][q] = 0.0f;

    load_tile(0, 0);
    load_tile(1, 1);

    for (int kt = 0; kt < G2_NT; kt++) {
        if (kt < G2_NT - 1) { CPA_WAIT(1); } else { CPA_WAIT(0); }
        __syncthreads();
        if (kt + 2 < G2_NT) load_tile(kt + 2, (kt + 2) % 3);

        uint32_t stage = sb + (kt % 3) * ST_SZ;
        #pragma unroll
        for (int ph = 0; ph < 3; ph++) {
            uint32_t abase = stage + ((ph == 2) ? 8192 : 0);
            uint32_t bbase = stage + ((ph == 1) ? 24576 : 16384);
            #pragma unroll
            for (int kh = 0; kh < 2; kh++) {
                uint32_t af[4][4];
                #pragma unroll
                for (int mt = 0; mt < 4; mt++) {
                    int row = wm + mt * 16 + (lid & 15);
                    int ch  = (kh * 2 + (lid >> 4)) ^ ((row >> 1) & 3);
                    ldm_x4(af[mt][0], af[mt][1], af[mt][2], af[mt][3],
                           abase + (uint32_t)(row * 64 + ch * 16));
                }
                uint32_t bfr[2][4];
                #pragma unroll
                for (int np = 0; np < 2; np++) {
                    int row = wn + np * 16 + ((lid >> 4) * 8) + (lid & 7);
                    int ch  = (kh * 2 + ((lid >> 3) & 1)) ^ ((row >> 1) & 3);
                    ldm_x4(bfr[np][0], bfr[np][1], bfr[np][2], bfr[np][3],
                           bbase + (uint32_t)(row * 64 + ch * 16));
                }
                #pragma unroll
                for (int mt = 0; mt < 4; mt++)
                    #pragma unroll
                    for (int nt = 0; nt < 4; nt++)
                        mma_bf16(acc[mt][nt], af[mt], &bfr[nt >> 1][(nt & 1) * 2]);
            }
        }
    }

    /* ---- fused epilogue ---- */
    __syncthreads();   /* all mma fragment reads done; smem is ours */

    float* st = reinterpret_cast<float*>(smem);          /* 128 x 132 floats */
    #pragma unroll
    for (int nt = 0; nt < 4; nt++) {
        int col = wn + nt * 8 + (lid & 3) * 2;
        float bx = __ldg(b2 + 1024 + n0 + col);
        float by = __ldg(b2 + 1024 + n0 + col + 1);
        #pragma unroll
        for (int mt = 0; mt < 4; mt++) {
            int r0 = wm + mt * 16 + (lid >> 2);
            st[r0 * 132 + col]           = acc[mt][nt][0] + bx;
            st[r0 * 132 + col + 1]       = acc[mt][nt][1] + by;
            st[(r0 + 8) * 132 + col]     = acc[mt][nt][2] + bx;
            st[(r0 + 8) * 132 + col + 1] = acc[mt][nt][3] + by;
        }
    }
    __syncthreads();

    float term_sum = 0.0f;

    #pragma unroll
    for (int s2 = 0; s2 < 2; s2++) {
        const int site = tid + 256 * s2;        /* 0..511 */
        const int row_local = site & 127;
        const int ch_local  = site >> 7;        /* 0..3 */
        const int c = 32 + (n0 >> 5) + ch_local;
        const int row = m0 + row_local;

        float p[32];
        {
            const float* pp = st + row_local * 132 + ch_local * 32;
            #pragma unroll
            for (int q = 0; q < 32; q += 4) {
                float4 v = *reinterpret_cast<const float4*>(pp + q);
                p[q] = v.x; p[q+1] = v.y; p[q+2] = v.z; p[q+3] = v.w;
            }
        }

        const float zc = z[(size_t)row * C_ + c];
        const float maskv = __ldg(mask + c);
        const float cm = 1.0f - maskv;

        float sf = expf(__ldg(sfv + c));
        float t  = p[0] * cm;
        float ls = tanhf(p[1] / fmaxf(sf, 1.0f)) * sf * cm;

        float lp[K_], aa[K_], bbk[K_];
        float mx0 = -INFINITY, mxA = -INFINITY, mxB = -INFINITY;
        #pragma unroll
        for (int k = 0; k < K_; k++) { lp[k] = p[2 + k] * cm; mx0 = fmaxf(mx0, lp[k]); }
        #pragma unroll
        for (int k = 0; k < K_; k++) {
            float msf = expf(__ldg(msfv + c * K_ + k));
            float mls = tanhf(p[22 + k] / fmaxf(msf, 1.0f)) * msf * cm;
            float mt  = p[12 + k] * cm;
            float u   = (zc - mt) * expf(-mls);
            float e   = expf(-fabsf(u));
            float l1  = log1pf(e);
            float logsig = fminf(u, 0.0f) - l1;
            float sp     = fmaxf(u, 0.0f) + l1;
            aa[k]  = lp[k] + logsig;
            bbk[k] = lp[k] + u - mls - 2.0f * sp;
            mxA = fmaxf(mxA, aa[k]);
            mxB = fmaxf(mxB, bbk[k]);
        }
        float s0 = 0.0f, sA = 0.0f, sB = 0.0f;
        #pragma unroll
        for (int k = 0; k < K_; k++) {
            s0 += expf(lp[k] - mx0); sA += expf(aa[k] - mxA); sB += expf(bbk[k] - mxB);
        }
        float lse0 = mx0 + logf(s0);
        float lseA = mxA + logf(sA);
        float lseB = mxB + logf(sB);

        float log_cdf = lseA - lse0;
        float p_cdf   = expf(log_cdf);
        float z_logit = -logf(fmaxf(1.0f / p_cdf - 1.0f, 1e-22f));
        float mixt_ldj = -logf(fmaxf(p_cdf, 1e-22f)) - logf(fmaxf(1.0f - p_cdf, 1e-22f));
        float logistic_ldj = lseB - lse0;

        float zo = (z_logit + t) * expf(ls);
        zo = zo * cm + zc * maskv;
        out[(size_t)row * C_ + c] = zo;

        term_sum += cm * (ls + mixt_ldj + logistic_ldj);
    }

    /* low-half z_out (channels 0..31): bx==0 CTAs cover it */
    if (blockIdx.x == 0) {
        #pragma unroll
        for (int s2 = 0; s2 < 16; s2++) {
            int idx = tid + 256 * s2;     /* 0..4095 */
            int rl = idx >> 5, cl = idx & 31;
            out[(size_t)(m0 + rl) * C_ + cl] =
                z[(size_t)(m0 + rl) * C_ + cl] * __ldg(mask + cl);
        }
    }

    /* deterministic per-CTA ldj reduction (red buffer above the stage) */
    float* red = reinterpret_cast<float*>(smem + 69632);
    red[tid] = term_sum;
    __syncthreads();
    for (int s = 128; s > 0; s >>= 1) {
        if (tid < s) red[tid] += red[tid + s];
        __syncthreads();
    }
    if (tid == 0) g_part[blockIdx.y * 8 + blockIdx.x] = red[0];
}

/* final ldj: one block per batch, fixed-order sum of 64 CTA partials */
__global__ __launch_bounds__(64) void reduce_kernel(float* __restrict__ out)
{
    __shared__ float red[64];
    const int b = blockIdx.x, tid = threadIdx.x;
    red[tid] = g_part[b * 64 + tid];
    __syncthreads();
    for (int s = 32; s > 0; s >>= 1) {
        if (tid < s) red[tid] += red[tid + s];
        __syncthreads();
    }
    if (tid == 0) out[(size_t)M_ * C_ + b] = red[0];
}

extern "C" void kernel_launch(void* const* d_in, const int* in_sizes, int n_in,
                              void* d_out, int out_size)
{
    const float* z    = (const float*)d_in[0];
    const float* mask = (const float*)d_in[1];
    const float* w1   = (const float*)d_in[2];
    const float* b1   = (const float*)d_in[3];
    const float* w2   = (const float*)d_in[4];
    const float* b2   = (const float*)d_in[5];
    const float* sfv  = (const float*)d_in[6];
    const float* msfv = (const float*)d_in[7];
    float* out = (float*)d_out;

    cudaFuncSetAttribute(gemm2_fused_kernel,
                         cudaFuncAttributeMaxDynamicSharedMemorySize, G2_SMEM);

    dim3 gt(NOUT / 32, H_ / 32);
    w2t_kernel<<<gt, 256>>>(w2);

    dim3 g1(H_ / 128, M_ / 64);
    gemm1_kernel<<<g1, 256>>>(z, mask, w1, b1);

    dim3 g2(NOUT / 128, M_ / 128);   /* (8, 128) = 1024 CTAs */
    gemm2_fused_kernel<<<g2, 256, G2_SMEM>>>(b2, z, mask, sfv, msfv, out);

    reduce_kernel<<<B_, 64>>>(out);
}

// round 14
// speedup vs baseline: 1.1765x; 1.0311x over previous
#include <cuda_runtime.h>
#include <cuda_bf16.h>
#include <math.h>
#include <stdint.h>

#define B_   16
#define L_   1024
#define C_   64
#define K_   10
#define H_   1024
#define M_   (B_*L_)        /* 16384 rows */
#define NOUT 1024           /* active half of COUT=2048 */
#define COUT_ 2048

/* scratch (allocation-free rule: __device__ globals) */
__device__ __nv_bfloat16 g_ha_hi[M_ * H_];   /* 32 MB */
__device__ __nv_bfloat16 g_ha_lo[M_ * H_];   /* 32 MB */
__device__ __nv_bfloat16 g_w2_hi[NOUT * H_]; /*  2 MB: [n][k] */
__device__ __nv_bfloat16 g_w2_lo[NOUT * H_]; /*  2 MB */
__device__ float g_part[1024];               /* per-CTA ldj partials */

/* ---------------- helpers ---------------- */
__device__ __forceinline__ uint32_t smem_u32(const void* p) {
    uint32_t a;
    asm("{ .reg .u64 t; cvta.to.shared.u64 t, %1; cvt.u32.u64 %0, t; }" : "=r"(a) : "l"(p));
    return a;
}
#define CPA16(dst, src) asm volatile("cp.async.cg.shared.global [%0], [%1], 16;" :: "r"(dst), "l"(src))
#define CPA_COMMIT()    asm volatile("cp.async.commit_group;")
#define CPA_WAIT(n)     asm volatile("cp.async.wait_group %0;" :: "n"(n) : "memory")

__device__ __forceinline__ void ldm_x4(uint32_t& r0, uint32_t& r1, uint32_t& r2, uint32_t& r3,
                                       uint32_t addr) {
    asm volatile("ldmatrix.sync.aligned.m8n8.x4.shared.b16 {%0,%1,%2,%3}, [%4];"
                 : "=r"(r0), "=r"(r1), "=r"(r2), "=r"(r3) : "r"(addr));
}
__device__ __forceinline__ void mma_bf16(float* d, const uint32_t* a, const uint32_t* b) {
    asm volatile("mma.sync.aligned.m16n8k16.row.col.f32.bf16.bf16.f32 "
                 "{%0,%1,%2,%3}, {%4,%5,%6,%7}, {%8,%9}, {%0,%1,%2,%3};"
                 : "+f"(d[0]), "+f"(d[1]), "+f"(d[2]), "+f"(d[3])
                 : "r"(a[0]), "r"(a[1]), "r"(a[2]), "r"(a[3]), "r"(b[0]), "r"(b[1]));
}

/* fast tanh for gelu only (bias decorrelated by downstream GEMM) */
__device__ __forceinline__ float fast_tanh(float x) {
    float e = __expf(2.0f * x);
    return 1.0f - 2.0f / (e + 1.0f);
}
__device__ __forceinline__ float gelu_tanh(float x) {
    const float k0 = 0.7978845608028654f, k1 = 0.044715f;
    float t = fast_tanh(k0 * (x + k1 * x * x * x));
    return 0.5f * x * (1.0f + t);
}

/* ------------------------------------------------------------------ */
/* w2 transpose+split: hi/lo bf16 of w2[k][1024+n] at [n][k]           */
/* ------------------------------------------------------------------ */
__global__ __launch_bounds__(256) void w2t_kernel(const float* __restrict__ w2)
{
    __shared__ float t[32][33];
    int k0 = blockIdx.y * 32, n0 = blockIdx.x * 32;
    int tx = threadIdx.x & 31, ty = threadIdx.x >> 5;   /* 32 x 8 */
    #pragma unroll
    for (int j = 0; j < 32; j += 8)
        t[ty + j][tx] = w2[(size_t)(k0 + ty + j) * COUT_ + 1024 + n0 + tx];
    __syncthreads();
    #pragma unroll
    for (int j = 0; j < 32; j += 8) {
        float v = t[tx][ty + j];
        __nv_bfloat16 hi = __float2bfloat16(v);
        __nv_bfloat16 lo = __float2bfloat16(v - __bfloat162float(hi));
        size_t idx = (size_t)(n0 + ty + j) * H_ + k0 + tx;
        g_w2_hi[idx] = hi;
        g_w2_lo[idx] = lo;
    }
}

/* ------------------------------------------------------------------ */
/* GEMM1: h = gelu(z_in @ w1 + b1), K truncated to 32 (mask zeroes top)*/
/* epilogue stores bf16 hi + lo                                        */
/* ------------------------------------------------------------------ */
__global__ __launch_bounds__(256) void gemm1_kernel(
    const float* __restrict__ z, const float* __restrict__ mask,
    const float* __restrict__ w1, const float* __restrict__ b1)
{
    __shared__ float zs[32][64];
    __shared__ float ws[32][128];

    const int m0 = blockIdx.y * 64;
    const int n0 = blockIdx.x * 128;
    const int tid = threadIdx.x;

    #pragma unroll
    for (int s = 0; s < 2; s++) {
        int idx = tid + 256 * s;
        int row = idx >> 3, q = idx & 7;
        float4 v = *reinterpret_cast<const float4*>(z + (size_t)(m0 + row) * C_ + q * 4);
        int c = q * 4;
        zs[c + 0][row] = v.x * __ldg(mask + c + 0);
        zs[c + 1][row] = v.y * __ldg(mask + c + 1);
        zs[c + 2][row] = v.z * __ldg(mask + c + 2);
        zs[c + 3][row] = v.w * __ldg(mask + c + 3);
    }
    #pragma unroll
    for (int s = 0; s < 4; s++) {
        int idx = tid + 256 * s;
        int c = idx >> 5, j = idx & 31;
        *reinterpret_cast<float4*>(&ws[c][j * 4]) =
            *reinterpret_cast<const float4*>(w1 + (size_t)c * H_ + n0 + j * 4);
    }
    __syncthreads();

    const int ty = tid >> 5, tx = tid & 31;
    float acc[8][4];
    #pragma unroll
    for (int i = 0; i < 8; i++)
        #pragma unroll
        for (int j = 0; j < 4; j++) acc[i][j] = 0.0f;

    #pragma unroll 8
    for (int c = 0; c < 32; c++) {
        float4 b4 = *reinterpret_cast<float4*>(&ws[c][tx * 4]);
        float a[8];
        *reinterpret_cast<float4*>(a)     = *reinterpret_cast<float4*>(&zs[c][ty * 8]);
        *reinterpret_cast<float4*>(a + 4) = *reinterpret_cast<float4*>(&zs[c][ty * 8 + 4]);
        #pragma unroll
        for (int i = 0; i < 8; i++) {
            acc[i][0] += a[i] * b4.x; acc[i][1] += a[i] * b4.y;
            acc[i][2] += a[i] * b4.z; acc[i][3] += a[i] * b4.w;
        }
    }

    float4 bb = *reinterpret_cast<const float4*>(b1 + n0 + tx * 4);
    #pragma unroll
    for (int i = 0; i < 8; i++) {
        int row = m0 + ty * 8 + i;
        float o[4];
        o[0] = gelu_tanh(acc[i][0] + bb.x);
        o[1] = gelu_tanh(acc[i][1] + bb.y);
        o[2] = gelu_tanh(acc[i][2] + bb.z);
        o[3] = gelu_tanh(acc[i][3] + bb.w);
        __nv_bfloat162 h0, h1, l0, l1;
        h0.x = __float2bfloat16(o[0]); h0.y = __float2bfloat16(o[1]);
        h1.x = __float2bfloat16(o[2]); h1.y = __float2bfloat16(o[3]);
        l0.x = __float2bfloat16(o[0] - __bfloat162float(h0.x));
        l0.y = __float2bfloat16(o[1] - __bfloat162float(h0.y));
        l1.x = __float2bfloat16(o[2] - __bfloat162float(h1.x));
        l1.y = __float2bfloat16(o[3] - __bfloat162float(h1.y));
        size_t off = (size_t)row * H_ + n0 + tx * 4;
        *reinterpret_cast<uint2*>(g_ha_hi + off) = make_uint2(*(uint32_t*)&h0, *(uint32_t*)&h1);
        *reinterpret_cast<uint2*>(g_ha_lo + off) = make_uint2(*(uint32_t*)&l0, *(uint32_t*)&l1);
    }
}

/* ------------------------------------------------------------------ */
/* GEMM2 + fused post: 3xBF16 split-precision, BM=128 BN=128 BK=32     */
/* kh-outer mainloop with ldmatrix dedup (12 ldm/kh instead of 18):    */
/*   load A_hi,B_hi,B_lo -> mma(Ahi,Bhi), mma(Ahi,Blo);                */
/*   reload A frags from A_lo -> mma(Alo,Bhi)                          */
/* epilogue: acc+bias -> smem -> mixture-CDF math (accurate libm)      */
/* ------------------------------------------------------------------ */
#define G2_NT 32
#define ST_SZ  32768
#define G2_SMEM (3 * ST_SZ)   /* 96 KB dynamic */

__global__ __launch_bounds__(256, 2) void gemm2_fused_kernel(
    const float* __restrict__ b2,
    const float* __restrict__ z, const float* __restrict__ mask,
    const float* __restrict__ sfv, const float* __restrict__ msfv,
    float* __restrict__ out)
{
    extern __shared__ __align__(16) char smem[];
    const uint32_t sb = smem_u32(smem);

    const int tid = threadIdx.x;
    const int wid = tid >> 5, lid = tid & 31;
    const int m0 = blockIdx.y * 128;
    const int n0 = blockIdx.x * 128;
    const int wm = (wid >> 2) * 64;
    const int wn = (wid & 3) * 32;

    const __nv_bfloat16* srcs[4] = {
        g_ha_hi + (size_t)m0 * H_,
        g_ha_lo + (size_t)m0 * H_,
        g_w2_hi + (size_t)n0 * H_,
        g_w2_lo + (size_t)n0 * H_
    };

    auto load_tile = [&](int kt, int st) {
        uint32_t base = sb + st * ST_SZ;
        #pragma unroll
        for (int s = 0; s < 8; s++) {
            int idx = tid + 256 * s;          /* 0..2047 */
            int part = idx >> 9;              /* 0..3 */
            int i2 = idx & 511;
            int row = i2 >> 2, seg = i2 & 3;
            uint32_t dst = (uint32_t)(part * 8192 + row * 64 + ((seg ^ ((row >> 1) & 3)) << 4));
            CPA16(base + dst, srcs[part] + (size_t)row * H_ + kt * 32 + seg * 8);
        }
        CPA_COMMIT();
    };

    float acc[4][4][4];
    #pragma unroll
    for (int i = 0; i < 4; i++)
        #pragma unroll
        for (int j = 0; j < 4; j++)
            #pragma unroll
            for (int q = 0; q < 4; q++) acc[i][j][q] = 0.0f;

    load_tile(0, 0);
    load_tile(1, 1);

    for (int kt = 0; kt < G2_NT; kt++) {
        if (kt < G2_NT - 1) { CPA_WAIT(1); } else { CPA_WAIT(0); }
        __syncthreads();
        if (kt + 2 < G2_NT) load_tile(kt + 2, (kt + 2) % 3);

        uint32_t stage = sb + (kt % 3) * ST_SZ;
        #pragma unroll
        for (int kh = 0; kh < 2; kh++) {
            /* B fragments: hi and lo, loaded once per kh */
            uint32_t bh[2][4], bl[2][4];
            #pragma unroll
            for (int np = 0; np < 2; np++) {
                int row = wn + np * 16 + ((lid >> 4) * 8) + (lid & 7);
                int ch  = (kh * 2 + ((lid >> 3) & 1)) ^ ((row >> 1) & 3);
                uint32_t off = (uint32_t)(row * 64 + ch * 16);
                ldm_x4(bh[np][0], bh[np][1], bh[np][2], bh[np][3], stage + 16384 + off);
                ldm_x4(bl[np][0], bl[np][1], bl[np][2], bl[np][3], stage + 24576 + off);
            }
            /* A_hi fragments */
            uint32_t af[4][4];
            #pragma unroll
            for (int mt = 0; mt < 4; mt++) {
                int row = wm + mt * 16 + (lid & 15);
                int ch  = (kh * 2 + (lid >> 4)) ^ ((row >> 1) & 3);
                ldm_x4(af[mt][0], af[mt][1], af[mt][2], af[mt][3],
                       stage + (uint32_t)(row * 64 + ch * 16));
            }
            /* phase 0: A_hi x B_hi ; phase 1: A_hi x B_lo */
            #pragma unroll
            for (int mt = 0; mt < 4; mt++)
                #pragma unroll
                for (int nt = 0; nt < 4; nt++)
                    mma_bf16(acc[mt][nt], af[mt], &bh[nt >> 1][(nt & 1) * 2]);
            #pragma unroll
            for (int mt = 0; mt < 4; mt++)
                #pragma unroll
                for (int nt = 0; nt < 4; nt++)
                    mma_bf16(acc[mt][nt], af[mt], &bl[nt >> 1][(nt & 1) * 2]);
            /* reload A frags from A_lo, phase 2: A_lo x B_hi */
            #pragma unroll
            for (int mt = 0; mt < 4; mt++) {
                int row = wm + mt * 16 + (lid & 15);
                int ch  = (kh * 2 + (lid >> 4)) ^ ((row >> 1) & 3);
                ldm_x4(af[mt][0], af[mt][1], af[mt][2], af[mt][3],
                       stage + 8192 + (uint32_t)(row * 64 + ch * 16));
            }
            #pragma unroll
            for (int mt = 0; mt < 4; mt++)
                #pragma unroll
                for (int nt = 0; nt < 4; nt++)
                    mma_bf16(acc[mt][nt], af[mt], &bh[nt >> 1][(nt & 1) * 2]);
        }
    }

    /* ---- fused epilogue ---- */
    __syncthreads();   /* all mma fragment reads done; smem is ours */

    float* st = reinterpret_cast<float*>(smem);          /* 128 x 132 floats */
    #pragma unroll
    for (int nt = 0; nt < 4; nt++) {
        int col = wn + nt * 8 + (lid & 3) * 2;
        float bx = __ldg(b2 + 1024 + n0 + col);
        float by = __ldg(b2 + 1024 + n0 + col + 1);
        #pragma unroll
        for (int mt = 0; mt < 4; mt++) {
            int r0 = wm + mt * 16 + (lid >> 2);
            st[r0 * 132 + col]           = acc[mt][nt][0] + bx;
            st[r0 * 132 + col + 1]       = acc[mt][nt][1] + by;
            st[(r0 + 8) * 132 + col]     = acc[mt][nt][2] + bx;
            st[(r0 + 8) * 132 + col + 1] = acc[mt][nt][3] + by;
        }
    }
    __syncthreads();

    float term_sum = 0.0f;

    #pragma unroll
    for (int s2 = 0; s2 < 2; s2++) {
        const int site = tid + 256 * s2;        /* 0..511 */
        const int row_local = site & 127;
        const int ch_local  = site >> 7;        /* 0..3 */
        const int c = 32 + (n0 >> 5) + ch_local;
        const int row = m0 + row_local;

        float p[32];
        {
            const float* pp = st + row_local * 132 + ch_local * 32;
            #pragma unroll
            for (int q = 0; q < 32; q += 4) {
                float4 v = *reinterpret_cast<const float4*>(pp + q);
                p[q] = v.x; p[q+1] = v.y; p[q+2] = v.z; p[q+3] = v.w;
            }
        }

        const float zc = z[(size_t)row * C_ + c];
        const float maskv = __ldg(mask + c);
        const float cm = 1.0f - maskv;

        float sf = expf(__ldg(sfv + c));
        float t  = p[0] * cm;
        float ls = tanhf(p[1] / fmaxf(sf, 1.0f)) * sf * cm;

        float lp[K_], aa[K_], bbk[K_];
        float mx0 = -INFINITY, mxA = -INFINITY, mxB = -INFINITY;
        #pragma unroll
        for (int k = 0; k < K_; k++) { lp[k] = p[2 + k] * cm; mx0 = fmaxf(mx0, lp[k]); }
        #pragma unroll
        for (int k = 0; k < K_; k++) {
            float msf = expf(__ldg(msfv + c * K_ + k));
            float mls = tanhf(p[22 + k] / fmaxf(msf, 1.0f)) * msf * cm;
            float mt  = p[12 + k] * cm;
            float u   = (zc - mt) * expf(-mls);
            float e   = expf(-fabsf(u));
            float l1  = log1pf(e);
            float logsig = fminf(u, 0.0f) - l1;
            float sp     = fmaxf(u, 0.0f) + l1;
            aa[k]  = lp[k] + logsig;
            bbk[k] = lp[k] + u - mls - 2.0f * sp;
            mxA = fmaxf(mxA, aa[k]);
            mxB = fmaxf(mxB, bbk[k]);
        }
        float s0 = 0.0f, sA = 0.0f, sB = 0.0f;
        #pragma unroll
        for (int k = 0; k < K_; k++) {
            s0 += expf(lp[k] - mx0); sA += expf(aa[k] - mxA); sB += expf(bbk[k] - mxB);
        }
        float lse0 = mx0 + logf(s0);
        float lseA = mxA + logf(sA);
        float lseB = mxB + logf(sB);

        float log_cdf = lseA - lse0;
        float p_cdf   = expf(log_cdf);
        float z_logit = -logf(fmaxf(1.0f / p_cdf - 1.0f, 1e-22f));
        float mixt_ldj = -logf(fmaxf(p_cdf, 1e-22f)) - logf(fmaxf(1.0f - p_cdf, 1e-22f));
        float logistic_ldj = lseB - lse0;

        float zo = (z_logit + t) * expf(ls);
        zo = zo * cm + zc * maskv;
        out[(size_t)row * C_ + c] = zo;

        term_sum += cm * (ls + mixt_ldj + logistic_ldj);
    }

    /* low-half z_out (channels 0..31): bx==0 CTAs cover it */
    if (blockIdx.x == 0) {
        #pragma unroll
        for (int s2 = 0; s2 < 16; s2++) {
            int idx = tid + 256 * s2;     /* 0..4095 */
            int rl = idx >> 5, cl = idx & 31;
            out[(size_t)(m0 + rl) * C_ + cl] =
                z[(size_t)(m0 + rl) * C_ + cl] * __ldg(mask + cl);
        }
    }

    /* deterministic per-CTA ldj reduction (red buffer above the stage) */
    float* red = reinterpret_cast<float*>(smem + 69632);
    red[tid] = term_sum;
    __syncthreads();
    for (int s = 128; s > 0; s >>= 1) {
        if (tid < s) red[tid] += red[tid + s];
        __syncthreads();
    }
    if (tid == 0) g_part[blockIdx.y * 8 + blockIdx.x] = red[0];
}

/* final ldj: one block per batch, fixed-order sum of 64 CTA partials */
__global__ __launch_bounds__(64) void reduce_kernel(float* __restrict__ out)
{
    __shared__ float red[64];
    const int b = blockIdx.x, tid = threadIdx.x;
    red[tid] = g_part[b * 64 + tid];
    __syncthreads();
    for (int s = 32; s > 0; s >>= 1) {
        if (tid < s) red[tid] += red[tid + s];
        __syncthreads();
    }
    if (tid == 0) out[(size_t)M_ * C_ + b] = red[0];
}

extern "C" void kernel_launch(void* const* d_in, const int* in_sizes, int n_in,
                              void* d_out, int out_size)
{
    const float* z    = (const float*)d_in[0];
    const float* mask = (const float*)d_in[1];
    const float* w1   = (const float*)d_in[2];
    const float* b1   = (const float*)d_in[3];
    const float* w2   = (const float*)d_in[4];
    const float* b2   = (const float*)d_in[5];
    const float* sfv  = (const float*)d_in[6];
    const float* msfv = (const float*)d_in[7];
    float* out = (float*)d_out;

    cudaFuncSetAttribute(gemm2_fused_kernel,
                         cudaFuncAttributeMaxDynamicSharedMemorySize, G2_SMEM);

    dim3 gt(NOUT / 32, H_ / 32);
    w2t_kernel<<<gt, 256>>>(w2);

    dim3 g1(H_ / 128, M_ / 64);
    gemm1_kernel<<<g1, 256>>>(z, mask, w1, b1);

    dim3 g2(NOUT / 128, M_ / 128);   /* (8, 128) = 1024 CTAs */
    gemm2_fused_kernel<<<g2, 256, G2_SMEM>>>(b2, z, mask, sfv, msfv, out);

    reduce_kernel<<<B_, 64>>>(out);
}

// round 15
// speedup vs baseline: 1.5477x; 1.3155x over previous
#include <cuda_runtime.h>
#include <cuda_bf16.h>
#include <cuda_fp16.h>
#include <math.h>
#include <stdint.h>

#define B_   16
#define L_   1024
#define C_   64
#define K_   10
#define H_   1024
#define M_   (B_*L_)        /* 16384 rows */
#define NOUT 1024           /* active half of COUT=2048 */
#define COUT_ 2048

/* scratch (allocation-free rule: __device__ globals) */
__device__ __half g_ha[M_ * H_];      /* 32 MB: gelu(z_in@w1+b1), fp16 */
__device__ __half g_w2_hi[NOUT * H_]; /*  2 MB: [n][k] fp16 hi */
__device__ __half g_w2_lo[NOUT * H_]; /*  2 MB: fp16 lo (w2 - hi) */
__device__ float g_part[1024];        /* per-CTA ldj partials */

/* ---------------- helpers ---------------- */
__device__ __forceinline__ uint32_t smem_u32(const void* p) {
    uint32_t a;
    asm("{ .reg .u64 t; cvta.to.shared.u64 t, %1; cvt.u32.u64 %0, t; }" : "=r"(a) : "l"(p));
    return a;
}
#define CPA16(dst, src) asm volatile("cp.async.cg.shared.global [%0], [%1], 16;" :: "r"(dst), "l"(src))
#define CPA_COMMIT()    asm volatile("cp.async.commit_group;")
#define CPA_WAIT(n)     asm volatile("cp.async.wait_group %0;" :: "n"(n) : "memory")

__device__ __forceinline__ void ldm_x4(uint32_t& r0, uint32_t& r1, uint32_t& r2, uint32_t& r3,
                                       uint32_t addr) {
    asm volatile("ldmatrix.sync.aligned.m8n8.x4.shared.b16 {%0,%1,%2,%3}, [%4];"
                 : "=r"(r0), "=r"(r1), "=r"(r2), "=r"(r3) : "r"(addr));
}
__device__ __forceinline__ void mma_f16(float* d, const uint32_t* a, const uint32_t* b) {
    asm volatile("mma.sync.aligned.m16n8k16.row.col.f32.f16.f16.f32 "
                 "{%0,%1,%2,%3}, {%4,%5,%6,%7}, {%8,%9}, {%0,%1,%2,%3};"
                 : "+f"(d[0]), "+f"(d[1]), "+f"(d[2]), "+f"(d[3])
                 : "r"(a[0]), "r"(a[1]), "r"(a[2]), "r"(a[3]), "r"(b[0]), "r"(b[1]));
}

/* fast tanh for gelu only (bias decorrelated by downstream GEMM) */
__device__ __forceinline__ float fast_tanh(float x) {
    float e = __expf(2.0f * x);
    return 1.0f - 2.0f / (e + 1.0f);
}
__device__ __forceinline__ float gelu_tanh(float x) {
    const float k0 = 0.7978845608028654f, k1 = 0.044715f;
    float t = fast_tanh(k0 * (x + k1 * x * x * x));
    return 0.5f * x * (1.0f + t);
}

/* ------------------------------------------------------------------ */
/* w2 transpose+split: fp16 hi/lo of w2[k][1024+n] at [n][k]           */
/* ------------------------------------------------------------------ */
__global__ __launch_bounds__(256) void w2t_kernel(const float* __restrict__ w2)
{
    __shared__ float t[32][33];
    int k0 = blockIdx.y * 32, n0 = blockIdx.x * 32;
    int tx = threadIdx.x & 31, ty = threadIdx.x >> 5;   /* 32 x 8 */
    #pragma unroll
    for (int j = 0; j < 32; j += 8)
        t[ty + j][tx] = w2[(size_t)(k0 + ty + j) * COUT_ + 1024 + n0 + tx];
    __syncthreads();
    #pragma unroll
    for (int j = 0; j < 32; j += 8) {
        float v = t[tx][ty + j];
        __half hi = __float2half(v);
        __half lo = __float2half(v - __half2float(hi));
        size_t idx = (size_t)(n0 + ty + j) * H_ + k0 + tx;
        g_w2_hi[idx] = hi;
        g_w2_lo[idx] = lo;
    }
}

/* ------------------------------------------------------------------ */
/* GEMM1: h = gelu(z_in @ w1 + b1), K truncated to 32 (mask zeroes top)*/
/* epilogue stores single fp16                                         */
/* ------------------------------------------------------------------ */
__global__ __launch_bounds__(256) void gemm1_kernel(
    const float* __restrict__ z, const float* __restrict__ mask,
    const float* __restrict__ w1, const float* __restrict__ b1)
{
    __shared__ float zs[32][64];
    __shared__ float ws[32][128];

    const int m0 = blockIdx.y * 64;
    const int n0 = blockIdx.x * 128;
    const int tid = threadIdx.x;

    #pragma unroll
    for (int s = 0; s < 2; s++) {
        int idx = tid + 256 * s;
        int row = idx >> 3, q = idx & 7;
        float4 v = *reinterpret_cast<const float4*>(z + (size_t)(m0 + row) * C_ + q * 4);
        int c = q * 4;
        zs[c + 0][row] = v.x * __ldg(mask + c + 0);
        zs[c + 1][row] = v.y * __ldg(mask + c + 1);
        zs[c + 2][row] = v.z * __ldg(mask + c + 2);
        zs[c + 3][row] = v.w * __ldg(mask + c + 3);
    }
    #pragma unroll
    for (int s = 0; s < 4; s++) {
        int idx = tid + 256 * s;
        int c = idx >> 5, j = idx & 31;
        *reinterpret_cast<float4*>(&ws[c][j * 4]) =
            *reinterpret_cast<const float4*>(w1 + (size_t)c * H_ + n0 + j * 4);
    }
    __syncthreads();

    const int ty = tid >> 5, tx = tid & 31;
    float acc[8][4];
    #pragma unroll
    for (int i = 0; i < 8; i++)
        #pragma unroll
        for (int j = 0; j < 4; j++) acc[i][j] = 0.0f;

    #pragma unroll 8
    for (int c = 0; c < 32; c++) {
        float4 b4 = *reinterpret_cast<float4*>(&ws[c][tx * 4]);
        float a[8];
        *reinterpret_cast<float4*>(a)     = *reinterpret_cast<float4*>(&zs[c][ty * 8]);
        *reinterpret_cast<float4*>(a + 4) = *reinterpret_cast<float4*>(&zs[c][ty * 8 + 4]);
        #pragma unroll
        for (int i = 0; i < 8; i++) {
            acc[i][0] += a[i] * b4.x; acc[i][1] += a[i] * b4.y;
            acc[i][2] += a[i] * b4.z; acc[i][3] += a[i] * b4.w;
        }
    }

    float4 bb = *reinterpret_cast<const float4*>(b1 + n0 + tx * 4);
    #pragma unroll
    for (int i = 0; i < 8; i++) {
        int row = m0 + ty * 8 + i;
        float o[4];
        o[0] = gelu_tanh(acc[i][0] + bb.x);
        o[1] = gelu_tanh(acc[i][1] + bb.y);
        o[2] = gelu_tanh(acc[i][2] + bb.z);
        o[3] = gelu_tanh(acc[i][3] + bb.w);
        __half2 h0 = __floats2half2_rn(o[0], o[1]);
        __half2 h1 = __floats2half2_rn(o[2], o[3]);
        size_t off = (size_t)row * H_ + n0 + tx * 4;
        *reinterpret_cast<uint2*>(g_ha + off) =
            make_uint2(*(uint32_t*)&h0, *(uint32_t*)&h1);
    }
}

/* ------------------------------------------------------------------ */
/* GEMM2 + fused post: 2-phase fp16, BM=128 BN=128 BK=32, 256 threads  */
/* A fp16 single; B fp16 hi+lo. Phases: A*B_hi + A*B_lo.               */
/* 3-stage cp.async pipeline (24KB stage). 8 warps = 2(M)x4(N).        */
/* epilogue: acc+bias -> smem -> mixture-CDF math (accurate libm)      */
/* ------------------------------------------------------------------ */
#define G2_NT 32
#define ST_SZ  24576
#define G2_SMEM (3 * ST_SZ)   /* 72 KB dynamic */

__global__ __launch_bounds__(256, 2) void gemm2_fused_kernel(
    const float* __restrict__ b2,
    const float* __restrict__ z, const float* __restrict__ mask,
    const float* __restrict__ sfv, const float* __restrict__ msfv,
    float* __restrict__ out)
{
    extern __shared__ __align__(16) char smem[];
    const uint32_t sb = smem_u32(smem);

    const int tid = threadIdx.x;
    const int wid = tid >> 5, lid = tid & 31;
    const int m0 = blockIdx.y * 128;
    const int n0 = blockIdx.x * 128;
    const int wm = (wid >> 2) * 64;
    const int wn = (wid & 3) * 32;

    const __half* srcs[3] = {
        g_ha    + (size_t)m0 * H_,
        g_w2_hi + (size_t)n0 * H_,
        g_w2_lo + (size_t)n0 * H_
    };

    /* load one K-tile: 3 parts x 512 chunks of 16B = 1536 chunks */
    auto load_tile = [&](int kt, int st) {
        uint32_t base = sb + st * ST_SZ;
        #pragma unroll
        for (int s = 0; s < 6; s++) {
            int idx = tid + 256 * s;          /* 0..1535 */
            int part = idx >> 9;              /* 0..2 */
            int i2 = idx & 511;
            int row = i2 >> 2, seg = i2 & 3;
            uint32_t dst = (uint32_t)(part * 8192 + row * 64 + ((seg ^ ((row >> 1) & 3)) << 4));
            CPA16(base + dst, srcs[part] + (size_t)row * H_ + kt * 32 + seg * 8);
        }
        CPA_COMMIT();
    };

    float acc[4][4][4];
    #pragma unroll
    for (int i = 0; i < 4; i++)
        #pragma unroll
        for (int j = 0; j < 4; j++)
            #pragma unroll
            for (int q = 0; q < 4; q++) acc[i][j][q] = 0.0f;

    load_tile(0, 0);
    load_tile(1, 1);

    for (int kt = 0; kt < G2_NT; kt++) {
        if (kt < G2_NT - 1) { CPA_WAIT(1); } else { CPA_WAIT(0); }
        __syncthreads();
        if (kt + 2 < G2_NT) load_tile(kt + 2, (kt + 2) % 3);

        uint32_t stage = sb + (kt % 3) * ST_SZ;
        #pragma unroll
        for (int kh = 0; kh < 2; kh++) {
            uint32_t bh[2][4], bl[2][4];
            #pragma unroll
            for (int np = 0; np < 2; np++) {
                int row = wn + np * 16 + ((lid >> 4) * 8) + (lid & 7);
                int ch  = (kh * 2 + ((lid >> 3) & 1)) ^ ((row >> 1) & 3);
                uint32_t off = (uint32_t)(row * 64 + ch * 16);
                ldm_x4(bh[np][0], bh[np][1], bh[np][2], bh[np][3], stage + 8192 + off);
                ldm_x4(bl[np][0], bl[np][1], bl[np][2], bl[np][3], stage + 16384 + off);
            }
            uint32_t af[4][4];
            #pragma unroll
            for (int mt = 0; mt < 4; mt++) {
                int row = wm + mt * 16 + (lid & 15);
                int ch  = (kh * 2 + (lid >> 4)) ^ ((row >> 1) & 3);
                ldm_x4(af[mt][0], af[mt][1], af[mt][2], af[mt][3],
                       stage + (uint32_t)(row * 64 + ch * 16));
            }
            /* phase 0: A x B_hi */
            #pragma unroll
            for (int mt = 0; mt < 4; mt++)
                #pragma unroll
                for (int nt = 0; nt < 4; nt++)
                    mma_f16(acc[mt][nt], af[mt], &bh[nt >> 1][(nt & 1) * 2]);
            /* phase 1: A x B_lo */
            #pragma unroll
            for (int mt = 0; mt < 4; mt++)
                #pragma unroll
                for (int nt = 0; nt < 4; nt++)
                    mma_f16(acc[mt][nt], af[mt], &bl[nt >> 1][(nt & 1) * 2]);
        }
    }

    /* ---- fused epilogue ---- */
    __syncthreads();   /* all mma fragment reads done; smem is ours */

    float* st = reinterpret_cast<float*>(smem);          /* 128 x 132 floats */
    #pragma unroll
    for (int nt = 0; nt < 4; nt++) {
        int col = wn + nt * 8 + (lid & 3) * 2;
        float bx = __ldg(b2 + 1024 + n0 + col);
        float by = __ldg(b2 + 1024 + n0 + col + 1);
        #pragma unroll
        for (int mt = 0; mt < 4; mt++) {
            int r0 = wm + mt * 16 + (lid >> 2);
            st[r0 * 132 + col]           = acc[mt][nt][0] + bx;
            st[r0 * 132 + col + 1]       = acc[mt][nt][1] + by;
            st[(r0 + 8) * 132 + col]     = acc[mt][nt][2] + bx;
            st[(r0 + 8) * 132 + col + 1] = acc[mt][nt][3] + by;
        }
    }
    __syncthreads();

    float term_sum = 0.0f;

    #pragma unroll
    for (int s2 = 0; s2 < 2; s2++) {
        const int site = tid + 256 * s2;        /* 0..511 */
        const int row_local = site & 127;
        const int ch_local  = site >> 7;        /* 0..3 */
        const int c = 32 + (n0 >> 5) + ch_local;
        const int row = m0 + row_local;

        float p[32];
        {
            const float* pp = st + row_local * 132 + ch_local * 32;
            #pragma unroll
            for (int q = 0; q < 32; q += 4) {
                float4 v = *reinterpret_cast<const float4*>(pp + q);
                p[q] = v.x; p[q+1] = v.y; p[q+2] = v.z; p[q+3] = v.w;
            }
        }

        const float zc = z[(size_t)row * C_ + c];
        const float maskv = __ldg(mask + c);
        const float cm = 1.0f - maskv;

        float sf = expf(__ldg(sfv + c));
        float t  = p[0] * cm;
        float ls = tanhf(p[1] / fmaxf(sf, 1.0f)) * sf * cm;

        float lp[K_], aa[K_], bbk[K_];
        float mx0 = -INFINITY, mxA = -INFINITY, mxB = -INFINITY;
        #pragma unroll
        for (int k = 0; k < K_; k++) { lp[k] = p[2 + k] * cm; mx0 = fmaxf(mx0, lp[k]); }
        #pragma unroll
        for (int k = 0; k < K_; k++) {
            float msf = expf(__ldg(msfv + c * K_ + k));
            float mls = tanhf(p[22 + k] / fmaxf(msf, 1.0f)) * msf * cm;
            float mt  = p[12 + k] * cm;
            float u   = (zc - mt) * expf(-mls);
            float e   = expf(-fabsf(u));
            float l1  = log1pf(e);
            float logsig = fminf(u, 0.0f) - l1;
            float sp     = fmaxf(u, 0.0f) + l1;
            aa[k]  = lp[k] + logsig;
            bbk[k] = lp[k] + u - mls - 2.0f * sp;
            mxA = fmaxf(mxA, aa[k]);
            mxB = fmaxf(mxB, bbk[k]);
        }
        float s0 = 0.0f, sA = 0.0f, sB = 0.0f;
        #pragma unroll
        for (int k = 0; k < K_; k++) {
            s0 += expf(lp[k] - mx0); sA += expf(aa[k] - mxA); sB += expf(bbk[k] - mxB);
        }
        float lse0 = mx0 + logf(s0);
        float lseA = mxA + logf(sA);
        float lseB = mxB + logf(sB);

        float log_cdf = lseA - lse0;
        float p_cdf   = expf(log_cdf);
        float z_logit = -logf(fmaxf(1.0f / p_cdf - 1.0f, 1e-22f));
        float mixt_ldj = -logf(fmaxf(p_cdf, 1e-22f)) - logf(fmaxf(1.0f - p_cdf, 1e-22f));
        float logistic_ldj = lseB - lse0;

        float zo = (z_logit + t) * expf(ls);
        zo = zo * cm + zc * maskv;
        out[(size_t)row * C_ + c] = zo;

        term_sum += cm * (ls + mixt_ldj + logistic_ldj);
    }

    /* low-half z_out (channels 0..31): bx==0 CTAs cover it */
    if (blockIdx.x == 0) {
        #pragma unroll
        for (int s2 = 0; s2 < 16; s2++) {
            int idx = tid + 256 * s2;     /* 0..4095 */
            int rl = idx >> 5, cl = idx & 31;
            out[(size_t)(m0 + rl) * C_ + cl] =
                z[(size_t)(m0 + rl) * C_ + cl] * __ldg(mask + cl);
        }
    }

    /* deterministic per-CTA ldj reduction (red buffer above the stage) */
    float* red = reinterpret_cast<float*>(smem + 69632);
    red[tid] = term_sum;
    __syncthreads();
    for (int s = 128; s > 0; s >>= 1) {
        if (tid < s) red[tid] += red[tid + s];
        __syncthreads();
    }
    if (tid == 0) g_part[blockIdx.y * 8 + blockIdx.x] = red[0];
}

/* final ldj: one block per batch, fixed-order sum of 64 CTA partials */
__global__ __launch_bounds__(64) void reduce_kernel(float* __restrict__ out)
{
    __shared__ float red[64];
    const int b = blockIdx.x, tid = threadIdx.x;
    red[tid] = g_part[b * 64 + tid];
    __syncthreads();
    for (int s = 32; s > 0; s >>= 1) {
        if (tid < s) red[tid] += red[tid + s];
        __syncthreads();
    }
    if (tid == 0) out[(size_t)M_ * C_ + b] = red[0];
}

extern "C" void kernel_launch(void* const* d_in, const int* in_sizes, int n_in,
                              void* d_out, int out_size)
{
    const float* z    = (const float*)d_in[0];
    const float* mask = (const float*)d_in[1];
    const float* w1   = (const float*)d_in[2];
    const float* b1   = (const float*)d_in[3];
    const float* w2   = (const float*)d_in[4];
    const float* b2   = (const float*)d_in[5];
    const float* sfv  = (const float*)d_in[6];
    const float* msfv = (const float*)d_in[7];
    float* out = (float*)d_out;

    cudaFuncSetAttribute(gemm2_fused_kernel,
                         cudaFuncAttributeMaxDynamicSharedMemorySize, G2_SMEM);

    dim3 gt(NOUT / 32, H_ / 32);
    w2t_kernel<<<gt, 256>>>(w2);

    dim3 g1(H_ / 128, M_ / 64);
    gemm1_kernel<<<g1, 256>>>(z, mask, w1, b1);

    dim3 g2(NOUT / 128, M_ / 128);   /* (8, 128) = 1024 CTAs */
    gemm2_fused_kernel<<<g2, 256, G2_SMEM>>>(b2, z, mask, sfv, msfv, out);

    reduce_kernel<<<B_, 64>>>(out);
}

// round 17
// speedup vs baseline: 1.5895x; 1.0270x over previous
#include <cuda_runtime.h>
#include <cuda_bf16.h>
#include <cuda_fp16.h>
#include <math.h>
#include <stdint.h>

#define B_   16
#define L_   1024
#define C_   64
#define K_   10
#define H_   1024
#define M_   (B_*L_)        /* 16384 rows */
#define NOUT 1024           /* active half of COUT=2048 */
#define COUT_ 2048

/* scratch (allocation-free rule: __device__ globals) */
__device__ __half g_ha[M_ * H_];      /* 32 MB: gelu(z_in@w1+b1), fp16 */
__device__ __half g_w2_hi[NOUT * H_]; /*  2 MB: [n][k] fp16 hi */
__device__ __half g_w2_lo[NOUT * H_]; /*  2 MB: fp16 lo (w2 - hi) */
__device__ __half g_za[M_ * 32];      /*  1 MB: z*mask (first 32 ch), fp16 */
__device__ __half g_w1t[H_ * 32];     /* 64 KB: w1t[n][c] = w1[c][n], c<32 */
__device__ float g_part[1024];        /* per-CTA ldj partials */

/* ---------------- helpers ---------------- */
__device__ __forceinline__ uint32_t smem_u32(const void* p) {
    uint32_t a;
    asm("{ .reg .u64 t; cvta.to.shared.u64 t, %1; cvt.u32.u64 %0, t; }" : "=r"(a) : "l"(p));
    return a;
}
#define CPA16(dst, src) asm volatile("cp.async.cg.shared.global [%0], [%1], 16;" :: "r"(dst), "l"(src))
#define CPA_COMMIT()    asm volatile("cp.async.commit_group;")
#define CPA_WAIT(n)     asm volatile("cp.async.wait_group %0;" :: "n"(n) : "memory")

__device__ __forceinline__ void ldm_x4(uint32_t& r0, uint32_t& r1, uint32_t& r2, uint32_t& r3,
                                       uint32_t addr) {
    asm volatile("ldmatrix.sync.aligned.m8n8.x4.shared.b16 {%0,%1,%2,%3}, [%4];"
                 : "=r"(r0), "=r"(r1), "=r"(r2), "=r"(r3) : "r"(addr));
}
__device__ __forceinline__ void mma_f16(float* d, const uint32_t* a, const uint32_t* b) {
    asm volatile("mma.sync.aligned.m16n8k16.row.col.f32.f16.f16.f32 "
                 "{%0,%1,%2,%3}, {%4,%5,%6,%7}, {%8,%9}, {%0,%1,%2,%3};"
                 : "+f"(d[0]), "+f"(d[1]), "+f"(d[2]), "+f"(d[3])
                 : "r"(a[0]), "r"(a[1]), "r"(a[2]), "r"(a[3]), "r"(b[0]), "r"(b[1]));
}

/* fast tanh for gelu only (bias decorrelated by downstream GEMM) */
__device__ __forceinline__ float fast_tanh(float x) {
    float e = __expf(2.0f * x);
    return 1.0f - 2.0f / (e + 1.0f);
}
__device__ __forceinline__ float gelu_tanh(float x) {
    const float k0 = 0.7978845608028654f, k1 = 0.044715f;
    float t = fast_tanh(k0 * (x + k1 * x * x * x));
    return 0.5f * x * (1.0f + t);
}

/* ------------------------------------------------------------------ */
/* prep kernels                                                        */
/* ------------------------------------------------------------------ */
/* z*mask (first 32 channels) -> fp16 g_za[M][32] */
__global__ __launch_bounds__(256) void zprep_kernel(
    const float* __restrict__ z, const float* __restrict__ mask)
{
    int idx = blockIdx.x * 256 + threadIdx.x;   /* 0 .. M*8-1 */
    int row = idx >> 3, seg = idx & 7;
    float4 v = *reinterpret_cast<const float4*>(z + (size_t)row * C_ + seg * 4);
    int c = seg * 4;
    v.x *= __ldg(mask + c + 0);
    v.y *= __ldg(mask + c + 1);
    v.z *= __ldg(mask + c + 2);
    v.w *= __ldg(mask + c + 3);
    __half2 h0 = __floats2half2_rn(v.x, v.y);
    __half2 h1 = __floats2half2_rn(v.z, v.w);
    *reinterpret_cast<uint2*>(g_za + (size_t)row * 32 + c) =
        make_uint2(*(uint32_t*)&h0, *(uint32_t*)&h1);
}

/* w1t[n][c] = fp16(w1[c][n]) for c<32 */
__global__ __launch_bounds__(256) void w1t_kernel(const float* __restrict__ w1)
{
    __shared__ float t[32][33];
    int n0 = blockIdx.x * 32;
    int tx = threadIdx.x & 31, ty = threadIdx.x >> 5;   /* 32 x 8 */
    #pragma unroll
    for (int j = 0; j < 32; j += 8)
        t[ty + j][tx] = w1[(size_t)(ty + j) * H_ + n0 + tx];   /* t[c][n] */
    __syncthreads();
    #pragma unroll
    for (int j = 0; j < 32; j += 8)
        g_w1t[(size_t)(n0 + ty + j) * 32 + tx] = __float2half(t[tx][ty + j]);
}

/* w2 transpose+split: fp16 hi/lo of w2[k][1024+n] at [n][k] */
__global__ __launch_bounds__(256) void w2t_kernel(const float* __restrict__ w2)
{
    __shared__ float t[32][33];
    int k0 = blockIdx.y * 32, n0 = blockIdx.x * 32;
    int tx = threadIdx.x & 31, ty = threadIdx.x >> 5;   /* 32 x 8 */
    #pragma unroll
    for (int j = 0; j < 32; j += 8)
        t[ty + j][tx] = w2[(size_t)(k0 + ty + j) * COUT_ + 1024 + n0 + tx];
    __syncthreads();
    #pragma unroll
    for (int j = 0; j < 32; j += 8) {
        float v = t[tx][ty + j];
        __half hi = __float2half(v);
        __half lo = __float2half(v - __half2float(hi));
        size_t idx = (size_t)(n0 + ty + j) * H_ + k0 + tx;
        g_w2_hi[idx] = hi;
        g_w2_lo[idx] = lo;
    }
}

/* ------------------------------------------------------------------ */
/* GEMM1 (tensor): h = gelu(z_in @ w1 + b1), K=32 single tile          */
/* BM=128 BN=128, 256 threads, 8 warps = 2(M)x4(N), warp tile 64x32    */
/* ------------------------------------------------------------------ */
__global__ __launch_bounds__(256) void gemm1_mma_kernel(const float* __restrict__ b1)
{
    __shared__ __align__(16) char smem[16384];   /* A 8KB + B 8KB */
    const uint32_t sb = smem_u32(smem);

    const int tid = threadIdx.x;
    const int wid = tid >> 5, lid = tid & 31;
    const int m0 = blockIdx.y * 128;
    const int n0 = blockIdx.x * 128;
    const int wm = (wid >> 2) * 64;
    const int wn = (wid & 3) * 32;

    /* load A (g_za rows m0..+127, 64B/row) and B (g_w1t rows n0..+127) */
    {
        const __half* Ag = g_za  + (size_t)m0 * 32;
        const __half* Bg = g_w1t + (size_t)n0 * 32;
        #pragma unroll
        for (int s = 0; s < 4; s++) {
            int idx = tid + 256 * s;          /* 0..1023 */
            int i2 = idx & 511;
            int row = i2 >> 2, seg = i2 & 3;
            uint32_t dst = (uint32_t)(row * 64 + ((seg ^ ((row >> 1) & 3)) << 4));
            if (idx < 512)
                CPA16(sb + dst, Ag + (size_t)row * 32 + seg * 8);
            else
                CPA16(sb + 8192 + dst, Bg + (size_t)row * 32 + seg * 8);
        }
        CPA_COMMIT();
        CPA_WAIT(0);
        __syncthreads();
    }

    float acc[4][4][4];
    #pragma unroll
    for (int i = 0; i < 4; i++)
        #pragma unroll
        for (int j = 0; j < 4; j++)
            #pragma unroll
            for (int q = 0; q < 4; q++) acc[i][j][q] = 0.0f;

    #pragma unroll
    for (int kh = 0; kh < 2; kh++) {
        uint32_t bh[2][4];
        #pragma unroll
        for (int np = 0; np < 2; np++) {
            int row = wn + np * 16 + ((lid >> 4) * 8) + (lid & 7);
            int ch  = (kh * 2 + ((lid >> 3) & 1)) ^ ((row >> 1) & 3);
            ldm_x4(bh[np][0], bh[np][1], bh[np][2], bh[np][3],
                   sb + 8192 + (uint32_t)(row * 64 + ch * 16));
        }
        uint32_t af[4][4];
        #pragma unroll
        for (int mt = 0; mt < 4; mt++) {
            int row = wm + mt * 16 + (lid & 15);
            int ch  = (kh * 2 + (lid >> 4)) ^ ((row >> 1) & 3);
            ldm_x4(af[mt][0], af[mt][1], af[mt][2], af[mt][3],
                   sb + (uint32_t)(row * 64 + ch * 16));
        }
        #pragma unroll
        for (int mt = 0; mt < 4; mt++)
            #pragma unroll
            for (int nt = 0; nt < 4; nt++)
                mma_f16(acc[mt][nt], af[mt], &bh[nt >> 1][(nt & 1) * 2]);
    }

    /* epilogue: + b1, gelu, fp16 store */
    #pragma unroll
    for (int nt = 0; nt < 4; nt++) {
        int col = n0 + wn + nt * 8 + (lid & 3) * 2;
        float bx = __ldg(b1 + col);
        float by = __ldg(b1 + col + 1);
        #pragma unroll
        for (int mt = 0; mt < 4; mt++) {
            int r0 = m0 + wm + mt * 16 + (lid >> 2);
            __half2 v0 = __floats2half2_rn(gelu_tanh(acc[mt][nt][0] + bx),
                                           gelu_tanh(acc[mt][nt][1] + by));
            __half2 v1 = __floats2half2_rn(gelu_tanh(acc[mt][nt][2] + bx),
                                           gelu_tanh(acc[mt][nt][3] + by));
            *reinterpret_cast<__half2*>(g_ha + (size_t)r0 * H_ + col) = v0;
            *reinterpret_cast<__half2*>(g_ha + (size_t)(r0 + 8) * H_ + col) = v1;
        }
    }
}

/* ------------------------------------------------------------------ */
/* GEMM2 + fused post: 2-phase fp16 (A single, B hi+lo), BM=BN=128     */
/* 3-stage cp.async pipeline (24KB stage). 8 warps = 2(M)x4(N).        */
/* epilogue: acc+bias -> smem -> mixture-CDF math (accurate libm)      */
/* ------------------------------------------------------------------ */
#define G2_NT 32
#define ST_SZ  24576
#define G2_SMEM (3 * ST_SZ)   /* 72 KB dynamic */

__global__ __launch_bounds__(256, 2) void gemm2_fused_kernel(
    const float* __restrict__ b2,
    const float* __restrict__ z, const float* __restrict__ mask,
    const float* __restrict__ sfv, const float* __restrict__ msfv,
    float* __restrict__ out)
{
    extern __shared__ __align__(16) char smem[];
    const uint32_t sb = smem_u32(smem);

    const int tid = threadIdx.x;
    const int wid = tid >> 5, lid = tid & 31;
    const int m0 = blockIdx.y * 128;
    const int n0 = blockIdx.x * 128;
    const int wm = (wid >> 2) * 64;
    const int wn = (wid & 3) * 32;

    const __half* srcs[3] = {
        g_ha    + (size_t)m0 * H_,
        g_w2_hi + (size_t)n0 * H_,
        g_w2_lo + (size_t)n0 * H_
    };

    auto load_tile = [&](int kt, int st) {
        uint32_t base = sb + st * ST_SZ;
        #pragma unroll
        for (int s = 0; s < 6; s++) {
            int idx = tid + 256 * s;          /* 0..1535 */
            int part = idx >> 9;              /* 0..2 */
            int i2 = idx & 511;
            int row = i2 >> 2, seg = i2 & 3;
            uint32_t dst = (uint32_t)(part * 8192 + row * 64 + ((seg ^ ((row >> 1) & 3)) << 4));
            CPA16(base + dst, srcs[part] + (size_t)row * H_ + kt * 32 + seg * 8);
        }
        CPA_COMMIT();
    };

    float acc[4][4][4];
    #pragma unroll
    for (int i = 0; i < 4; i++)
        #pragma unroll
        for (int j = 0; j < 4; j++)
            #pragma unroll
            for (int q = 0; q < 4; q++) acc[i][j][q] = 0.0f;

    load_tile(0, 0);
    load_tile(1, 1);

    for (int kt = 0; kt < G2_NT; kt++) {
        if (kt < G2_NT - 1) { CPA_WAIT(1); } else { CPA_WAIT(0); }
        __syncthreads();
        if (kt + 2 < G2_NT) load_tile(kt + 2, (kt + 2) % 3);

        uint32_t stage = sb + (kt % 3) * ST_SZ;
        #pragma unroll
        for (int kh = 0; kh < 2; kh++) {
            uint32_t bh[2][4], bl[2][4];
            #pragma unroll
            for (int np = 0; np < 2; np++) {
                int row = wn + np * 16 + ((lid >> 4) * 8) + (lid & 7);
                int ch  = (kh * 2 + ((lid >> 3) & 1)) ^ ((row >> 1) & 3);
                uint32_t off = (uint32_t)(row * 64 + ch * 16);
                ldm_x4(bh[np][0], bh[np][1], bh[np][2], bh[np][3], stage + 8192 + off);
                ldm_x4(bl[np][0], bl[np][1], bl[np][2], bl[np][3], stage + 16384 + off);
            }
            uint32_t af[4][4];
            #pragma unroll
            for (int mt = 0; mt < 4; mt++) {
                int row = wm + mt * 16 + (lid & 15);
                int ch  = (kh * 2 + (lid >> 4)) ^ ((row >> 1) & 3);
                ldm_x4(af[mt][0], af[mt][1], af[mt][2], af[mt][3],
                       stage + (uint32_t)(row * 64 + ch * 16));
            }
            #pragma unroll
            for (int mt = 0; mt < 4; mt++)
                #pragma unroll
                for (int nt = 0; nt < 4; nt++)
                    mma_f16(acc[mt][nt], af[mt], &bh[nt >> 1][(nt & 1) * 2]);
            #pragma unroll
            for (int mt = 0; mt < 4; mt++)
                #pragma unroll
                for (int nt = 0; nt < 4; nt++)
                    mma_f16(acc[mt][nt], af[mt], &bl[nt >> 1][(nt & 1) * 2]);
        }
    }

    /* ---- fused epilogue ---- */
    __syncthreads();

    float* st = reinterpret_cast<float*>(smem);          /* 128 x 132 floats */
    #pragma unroll
    for (int nt = 0; nt < 4; nt++) {
        int col = wn + nt * 8 + (lid & 3) * 2;
        float bx = __ldg(b2 + 1024 + n0 + col);
        float by = __ldg(b2 + 1024 + n0 + col + 1);
        #pragma unroll
        for (int mt = 0; mt < 4; mt++) {
            int r0 = wm + mt * 16 + (lid >> 2);
            st[r0 * 132 + col]           = acc[mt][nt][0] + bx;
            st[r0 * 132 + col + 1]       = acc[mt][nt][1] + by;
            st[(r0 + 8) * 132 + col]     = acc[mt][nt][2] + bx;
            st[(r0 + 8) * 132 + col + 1] = acc[mt][nt][3] + by;
        }
    }
    __syncthreads();

    float term_sum = 0.0f;

    #pragma unroll
    for (int s2 = 0; s2 < 2; s2++) {
        const int site = tid + 256 * s2;        /* 0..511 */
        const int row_local = site & 127;
        const int ch_local  = site >> 7;        /* 0..3 */
        const int c = 32 + (n0 >> 5) + ch_local;
        const int row = m0 + row_local;

        float p[32];
        {
            const float* pp = st + row_local * 132 + ch_local * 32;
            #pragma unroll
            for (int q = 0; q < 32; q += 4) {
                float4 v = *reinterpret_cast<const float4*>(pp + q);
                p[q] = v.x; p[q+1] = v.y; p[q+2] = v.z; p[q+3] = v.w;
            }
        }

        const float zc = z[(size_t)row * C_ + c];
        const float maskv = __ldg(mask + c);
        const float cm = 1.0f - maskv;

        float sf = expf(__ldg(sfv + c));
        float t  = p[0] * cm;
        float ls = tanhf(p[1] / fmaxf(sf, 1.0f)) * sf * cm;

        float lp[K_], aa[K_], bbk[K_];
        float mx0 = -INFINITY, mxA = -INFINITY, mxB = -INFINITY;
        #pragma unroll
        for (int k = 0; k < K_; k++) { lp[k] = p[2 + k] * cm; mx0 = fmaxf(mx0, lp[k]); }
        #pragma unroll
        for (int k = 0; k < K_; k++) {
            float msf = expf(__ldg(msfv + c * K_ + k));
            float mls = tanhf(p[22 + k] / fmaxf(msf, 1.0f)) * msf * cm;
            float mt  = p[12 + k] * cm;
            float u   = (zc - mt) * expf(-mls);
            float e   = expf(-fabsf(u));
            float l1  = log1pf(e);
            float logsig = fminf(u, 0.0f) - l1;
            float sp     = fmaxf(u, 0.0f) + l1;
            aa[k]  = lp[k] + logsig;
            bbk[k] = lp[k] + u - mls - 2.0f * sp;
            mxA = fmaxf(mxA, aa[k]);
            mxB = fmaxf(mxB, bbk[k]);
        }
        float s0 = 0.0f, sA = 0.0f, sB = 0.0f;
        #pragma unroll
        for (int k = 0; k < K_; k++) {
            s0 += expf(lp[k] - mx0); sA += expf(aa[k] - mxA); sB += expf(bbk[k] - mxB);
        }
        float lse0 = mx0 + logf(s0);
        float lseA = mxA + logf(sA);
        float lseB = mxB + logf(sB);

        float log_cdf = lseA - lse0;
        float p_cdf   = expf(log_cdf);
        float z_logit = -logf(fmaxf(1.0f / p_cdf - 1.0f, 1e-22f));
        float mixt_ldj = -logf(fmaxf(p_cdf, 1e-22f)) - logf(fmaxf(1.0f - p_cdf, 1e-22f));
        float logistic_ldj = lseB - lse0;

        float zo = (z_logit + t) * expf(ls);
        zo = zo * cm + zc * maskv;
        out[(size_t)row * C_ + c] = zo;

        term_sum += cm * (ls + mixt_ldj + logistic_ldj);
    }

    /* low-half z_out (channels 0..31): bx==0 CTAs cover it */
    if (blockIdx.x == 0) {
        #pragma unroll
        for (int s2 = 0; s2 < 16; s2++) {
            int idx = tid + 256 * s2;     /* 0..4095 */
            int rl = idx >> 5, cl = idx & 31;
            out[(size_t)(m0 + rl) * C_ + cl] =
                z[(size_t)(m0 + rl) * C_ + cl] * __ldg(mask + cl);
        }
    }

    /* deterministic per-CTA ldj reduction */
    float* red = reinterpret_cast<float*>(smem + 69632);
    red[tid] = term_sum;
    __syncthreads();
    for (int s = 128; s > 0; s >>= 1) {
        if (tid < s) red[tid] += red[tid + s];
        __syncthreads();
    }
    if (tid == 0) g_part[blockIdx.y * 8 + blockIdx.x] = red[0];
}

/* final ldj: one block per batch, fixed-order sum of 64 CTA partials */
__global__ __launch_bounds__(64) void reduce_kernel(float* __restrict__ out)
{
    __shared__ float red[64];
    const int b = blockIdx.x, tid = threadIdx.x;
    red[tid] = g_part[b * 64 + tid];
    __syncthreads();
    for (int s = 32; s > 0; s >>= 1) {
        if (tid < s) red[tid] += red[tid + s];
        __syncthreads();
    }
    if (tid == 0) out[(size_t)M_ * C_ + b] = red[0];
}

extern "C" void kernel_launch(void* const* d_in, const int* in_sizes, int n_in,
                              void* d_out, int out_size)
{
    const float* z    = (const float*)d_in[0];
    const float* mask = (const float*)d_in[1];
    const float* w1   = (const float*)d_in[2];
    const float* b1   = (const float*)d_in[3];
    const float* w2   = (const float*)d_in[4];
    const float* b2   = (const float*)d_in[5];
    const float* sfv  = (const float*)d_in[6];
    const float* msfv = (const float*)d_in[7];
    float* out = (float*)d_out;

    cudaFuncSetAttribute(gemm2_fused_kernel,
                         cudaFuncAttributeMaxDynamicSharedMemorySize, G2_SMEM);

    zprep_kernel<<<M_ * 8 / 256, 256>>>(z, mask);
    w1t_kernel<<<H_ / 32, 256>>>(w1);
    dim3 gt(NOUT / 32, H_ / 32);
    w2t_kernel<<<gt, 256>>>(w2);

    dim3 g1(H_ / 128, M_ / 128);    /* (8, 128) */
    gemm1_mma_kernel<<<g1, 256>>>(b1);

    dim3 g2(NOUT / 128, M_ / 128);  /* (8, 128) */
    gemm2_fused_kernel<<<g2, 256, G2_SMEM>>>(b2, z, mask, sfv, msfv, out);

    reduce_kernel<<<B_, 64>>>(out);
}